// round 7
// baseline (speedup 1.0000x reference)
#include <cuda_runtime.h>
#include <mma.h>

using namespace nvcuda;

#define NB      262144
#define NTILES  (NB / 16)     // 16384 tiles of 16 batch rows
#define BLOCK   128
#define NWARPS  4
#define GRID    888           // 2 blocks/SM resident -> exactly 3 waves

using AF = wmma::fragment<wmma::matrix_a, 16, 16, 8, wmma::precision::tf32, wmma::row_major>;
using BF = wmma::fragment<wmma::matrix_b, 16, 16, 8, wmma::precision::tf32, wmma::row_major>;
using CF = wmma::fragment<wmma::accumulator, 16, 16, 8, float>;

__global__ void __launch_bounds__(BLOCK, 2)
hybridq_kernel(const float* __restrict__ xq, const float* __restrict__ xc,
               const float* __restrict__ qp,
               const float* __restrict__ W1, const float* __restrict__ b1,
               const float* __restrict__ W2, const float* __restrict__ b2,
               const float* __restrict__ W3, const float* __restrict__ b3,
               float* __restrict__ out)
{
    // Weight tiles, tf32-split (hi + lo), bias folded as an extra "ones" feature.
    // k-dims padded to multiples of 8 with zeros.
    __shared__ __align__(16) float w1hi[24][36], w1lo[24][36];  // k=24 (16 xc, q, one, 6 zero), n=32
    __shared__ __align__(16) float w2hi[40][20], w2lo[40][20];  // k=40 (32 h1, one, 7 zero),  n=16
    __shared__ __align__(16) float w3hi[24][20], w3lo[24][20];  // k=24 (16 h2, one, 7 zero),  n=16 (col0 live)
    // Per-warp fp32 workspaces.
    __shared__ __align__(16) float xs [NWARPS][16][28];  // cols: 0-15 xc, 16 q, 17 one, 18-23 zero
    __shared__ __align__(16) float h1s[NWARPS][16][44];  // cols: 0-31 h1, 32 one, 33-39 zero
    __shared__ __align__(16) float h2s[NWARPS][16][28];  // cols: 0-15 h2, 16 one, 17-23 zero

    const int tid = threadIdx.x;

    // ---- Stage split weights (once per block) ----
    for (int i = tid; i < 24 * 32; i += BLOCK) {
        int r = i >> 5, n = i & 31;
        float v = (r < 16) ? W1[(1 + r) * 32 + n]
                : (r == 16) ? W1[n]          // q feature row = W1[0][*]
                : (r == 17) ? b1[n] : 0.0f;  // ones feature row = bias
        float hi = wmma::__float_to_tf32(v);
        w1hi[r][n] = hi;
        w1lo[r][n] = wmma::__float_to_tf32(v - hi);
    }
    for (int i = tid; i < 40 * 16; i += BLOCK) {
        int r = i >> 4, n = i & 15;
        float v = (r < 32) ? W2[r * 16 + n] : (r == 32) ? b2[n] : 0.0f;
        float hi = wmma::__float_to_tf32(v);
        w2hi[r][n] = hi;
        w2lo[r][n] = wmma::__float_to_tf32(v - hi);
    }
    for (int i = tid; i < 24 * 16; i += BLOCK) {
        int r = i >> 4, n = i & 15;
        float v = 0.0f;
        if (n == 0) v = (r < 16) ? W3[r] : (r == 16) ? b3[0] : 0.0f;
        float hi = wmma::__float_to_tf32(v);
        w3hi[r][n] = hi;
        w3lo[r][n] = wmma::__float_to_tf32(v - hi);
    }
    __syncthreads();

    const int wid  = tid >> 5;
    const int lane = tid & 31;

    // ---- Init constant columns of workspaces (once) ----
    if (lane < 16) {
        xs[wid][lane][17] = 1.0f;
#pragma unroll
        for (int c = 18; c < 24; c++) xs[wid][lane][c] = 0.0f;
        h1s[wid][lane][32] = 1.0f;
#pragma unroll
        for (int c = 33; c < 40; c++) h1s[wid][lane][c] = 0.0f;
        h2s[wid][lane][16] = 1.0f;
#pragma unroll
        for (int c = 17; c < 24; c++) h2s[wid][lane][c] = 0.0f;
    }

    // ---- Persistent B fragments (values pre-rounded to tf32 in SMEM) ----
    BF b1f[3][2][2];   // [k-chunk][n-tile][hi/lo]
    BF b2f[5][2];
    BF b3f[3][2];
#pragma unroll
    for (int kc = 0; kc < 3; kc++)
#pragma unroll
        for (int nt = 0; nt < 2; nt++) {
            wmma::load_matrix_sync(b1f[kc][nt][0], &w1hi[kc * 8][nt * 16], 36);
            wmma::load_matrix_sync(b1f[kc][nt][1], &w1lo[kc * 8][nt * 16], 36);
        }
#pragma unroll
    for (int kc = 0; kc < 5; kc++) {
        wmma::load_matrix_sync(b2f[kc][0], &w2hi[kc * 8][0], 20);
        wmma::load_matrix_sync(b2f[kc][1], &w2lo[kc * 8][0], 20);
    }
#pragma unroll
    for (int kc = 0; kc < 3; kc++) {
        wmma::load_matrix_sync(b3f[kc][0], &w3hi[kc * 8][0], 20);
        wmma::load_matrix_sync(b3f[kc][1], &w3lo[kc * 8][0], 20);
    }

    const float qp1 = __ldg(qp + 1), qp2 = __ldg(qp + 2), qp3 = __ldg(qp + 3),
                qp4 = __ldg(qp + 4), qp5 = __ldg(qp + 5), qp6 = __ldg(qp + 6);

    for (int tile = blockIdx.x * NWARPS + wid; tile < NTILES; tile += GRID * NWARPS) {
        const int rbase = tile * 16;

        // ---- Stage xc [16 x 16] (2 lanes per row, float4 pairs) ----
        {
            int row = lane >> 1, half = lane & 1;
            const float4* p = (const float4*)(xc + (size_t)(rbase + row) * 16 + half * 8);
            float4 v0 = __ldg(p), v1 = __ldg(p + 1);
            float4* dst = (float4*)&xs[wid][row][half * 8];
            dst[0] = v0;
            dst[1] = v1;
        }
        // ---- Quantum feature: <Z0> = prod_{i=1..6} cos(xq_i + qp_i) ----
        // (CNOT-ring GF(2): qubit-0 output = parity(b1..b6); per-qubit factor
        //  cos^2 - sin^2 = cos(2h) = cos(x+w); qubit 0's own angle cancels.)
        if (lane < 16) {
            const float* xr = xq + (size_t)(rbase + lane) * 7;
            float v = __cosf(__ldg(xr + 1) + qp1);
            v *= __cosf(__ldg(xr + 2) + qp2);
            v *= __cosf(__ldg(xr + 3) + qp3);
            v *= __cosf(__ldg(xr + 4) + qp4);
            v *= __cosf(__ldg(xr + 5) + qp5);
            v *= __cosf(__ldg(xr + 6) + qp6);
            xs[wid][lane][16] = v;
        }
        __syncwarp();

        // ---- Layer 1: [16x24] x [24x32] ----
        CF c0, c1;
        wmma::fill_fragment(c0, 0.0f);
        wmma::fill_fragment(c1, 0.0f);
#pragma unroll
        for (int kc = 0; kc < 3; kc++) {
            AF a, ahi, alo;
            wmma::load_matrix_sync(a, &xs[wid][0][kc * 8], 28);
#pragma unroll
            for (int i = 0; i < a.num_elements; i++) {
                float hi = wmma::__float_to_tf32(a.x[i]);
                ahi.x[i] = hi;
                alo.x[i] = wmma::__float_to_tf32(a.x[i] - hi);
            }
            wmma::mma_sync(c0, ahi, b1f[kc][0][0], c0);
            wmma::mma_sync(c0, alo, b1f[kc][0][0], c0);
            wmma::mma_sync(c0, ahi, b1f[kc][0][1], c0);
            wmma::mma_sync(c1, ahi, b1f[kc][1][0], c1);
            wmma::mma_sync(c1, alo, b1f[kc][1][0], c1);
            wmma::mma_sync(c1, ahi, b1f[kc][1][1], c1);
        }
#pragma unroll
        for (int i = 0; i < c0.num_elements; i++) {
            c0.x[i] = fmaxf(c0.x[i], 0.0f);
            c1.x[i] = fmaxf(c1.x[i], 0.0f);
        }
        wmma::store_matrix_sync(&h1s[wid][0][0], c0, 44, wmma::mem_row_major);
        wmma::store_matrix_sync(&h1s[wid][0][16], c1, 44, wmma::mem_row_major);
        __syncwarp();

        // ---- Layer 2: [16x40] x [40x16] ----
        CF c2;
        wmma::fill_fragment(c2, 0.0f);
#pragma unroll
        for (int kc = 0; kc < 5; kc++) {
            AF a, ahi, alo;
            wmma::load_matrix_sync(a, &h1s[wid][0][kc * 8], 44);
#pragma unroll
            for (int i = 0; i < a.num_elements; i++) {
                float hi = wmma::__float_to_tf32(a.x[i]);
                ahi.x[i] = hi;
                alo.x[i] = wmma::__float_to_tf32(a.x[i] - hi);
            }
            wmma::mma_sync(c2, ahi, b2f[kc][0], c2);
            wmma::mma_sync(c2, alo, b2f[kc][0], c2);
            wmma::mma_sync(c2, ahi, b2f[kc][1], c2);
        }
#pragma unroll
        for (int i = 0; i < c2.num_elements; i++)
            c2.x[i] = fmaxf(c2.x[i], 0.0f);
        wmma::store_matrix_sync(&h2s[wid][0][0], c2, 28, wmma::mem_row_major);
        __syncwarp();

        // ---- Layer 3: [16x24] x [24x16] (only col 0 meaningful) ----
        CF c3;
        wmma::fill_fragment(c3, 0.0f);
#pragma unroll
        for (int kc = 0; kc < 3; kc++) {
            AF a, ahi, alo;
            wmma::load_matrix_sync(a, &h2s[wid][0][kc * 8], 28);
#pragma unroll
            for (int i = 0; i < a.num_elements; i++) {
                float hi = wmma::__float_to_tf32(a.x[i]);
                ahi.x[i] = hi;
                alo.x[i] = wmma::__float_to_tf32(a.x[i] - hi);
            }
            wmma::mma_sync(c3, ahi, b3f[kc][0], c3);
            wmma::mma_sync(c3, alo, b3f[kc][0], c3);
            wmma::mma_sync(c3, ahi, b3f[kc][1], c3);
        }
        wmma::store_matrix_sync(&h1s[wid][0][0], c3, 44, wmma::mem_row_major);
        __syncwarp();

        if (lane < 16)
            out[rbase + lane] = h1s[wid][lane][0];
        __syncwarp();   // out-reads done before next tile overwrites h1s
    }
}

extern "C" void kernel_launch(void* const* d_in, const int* in_sizes, int n_in,
                              void* d_out, int out_size)
{
    const float* xq = (const float*)d_in[0];
    const float* xc = (const float*)d_in[1];
    const float* qp = (const float*)d_in[2];
    const float* W1 = (const float*)d_in[3];
    const float* b1 = (const float*)d_in[4];
    const float* W2 = (const float*)d_in[5];
    const float* b2 = (const float*)d_in[6];
    const float* W3 = (const float*)d_in[7];
    const float* b3 = (const float*)d_in[8];
    float* out = (float*)d_out;

    hybridq_kernel<<<GRID, BLOCK>>>(xq, xc, qp, W1, b1, W2, b2, W3, b3, out);
}

// round 8
// speedup vs baseline: 2.1725x; 2.1725x over previous
#include <cuda_runtime.h>

#define NB 262144
#define NTHREADS (NB / 2)   // 2 elements per thread
#define BLOCK 128

typedef unsigned long long u64;

__device__ __forceinline__ u64 pack2(float lo, float hi) {
    u64 r; asm("mov.b64 %0, {%1,%2};" : "=l"(r) : "f"(lo), "f"(hi)); return r;
}
__device__ __forceinline__ void unpack2(u64 v, float& lo, float& hi) {
    asm("mov.b64 {%0,%1}, %2;" : "=f"(lo), "=f"(hi) : "l"(v));
}
__device__ __forceinline__ u64 fma2(u64 a, u64 b, u64 c) {
    u64 r; asm("fma.rn.f32x2 %0, %1, %2, %3;" : "=l"(r) : "l"(a), "l"(b), "l"(c)); return r;
}
__device__ __forceinline__ u64 mul2(u64 a, u64 b) {
    u64 r; asm("mul.rn.f32x2 %0, %1, %2;" : "=l"(r) : "l"(a), "l"(b)); return r;
}
__device__ __forceinline__ u64 relu2(u64 x) {
    float lo, hi; unpack2(x, lo, hi);
    lo = fmaxf(lo, 0.0f); hi = fmaxf(hi, 0.0f);
    return pack2(lo, hi);
}

__global__ __launch_bounds__(BLOCK, 5)
void hybridq_kernel(const float* __restrict__ xq, const float* __restrict__ xc,
                    const float* __restrict__ qp,
                    const float* __restrict__ W1, const float* __restrict__ b1,
                    const float* __restrict__ W2, const float* __restrict__ b2,
                    const float* __restrict__ W3, const float* __restrict__ b3,
                    float* __restrict__ out)
{
    // Feature-pair-packed weights: each u64 holds TWO DISTINCT weights.
    // All lanes read identical SMEM addresses -> broadcast (1 wavefront/LDS).
    __shared__ u64 sW1[32][8];   // [k][pair j] = (W1[1+2j][k], W1[2+2j][k])
    __shared__ u64 sWqb[32];     // (W1[0][k], b1[k])
    __shared__ u64 sW2[32 * 8];  // W2 native row-major viewed as u64 pairs
    __shared__ u64 sW3[8];       // W3 native pairs
    __shared__ u64 sb2[8];       // b2 native pairs

    const int tid = threadIdx.x;
    for (int i = tid; i < 32 * 8; i += BLOCK) {
        int k = i / 8, j = i % 8;
        sW1[k][j] = pack2(W1[(1 + 2 * j) * 32 + k], W1[(2 + 2 * j) * 32 + k]);
    }
    for (int i = tid; i < 32 * 8; i += BLOCK)
        sW2[i] = ((const u64*)W2)[i];
    if (tid < 32) sWqb[tid] = pack2(W1[tid], b1[tid]);   // W1[0*32+k], b1[k]
    if (tid < 8) {
        sW3[tid] = ((const u64*)W3)[tid];
        sb2[tid] = ((const u64*)b2)[tid];
    }
    __syncthreads();

    const int t  = blockIdx.x * BLOCK + tid;
    const int e0 = t;
    const int e1 = t + NTHREADS;

    // ---- Quantum feature: <Z0> = prod_{i=1..6} cos(x_q[i] + qp[i]) ----
    // (CNOT-ring GF(2): qubit-0 output = parity(b1..b6); per-qubit factor
    //  cos^2(h)-sin^2(h) = cos(2h) = cos(x+w); qubit 0's own angle cancels.)
    float q[2] = {1.0f, 1.0f};
#pragma unroll
    for (int i = 1; i < 7; i++) {
        float w = __ldg(qp + i);
        q[0] *= __cosf(__ldg(xq + (size_t)e0 * 7 + i) + w);
        q[1] *= __cosf(__ldg(xq + (size_t)e1 * 7 + i) + w);
    }

    // ---- xc features: native f32x2 pairs straight from LDG.128 ----
    u64 in[2][8];
    {
        const ulonglong2* c0 = (const ulonglong2*)(xc + (size_t)e0 * 16);
        const ulonglong2* c1 = (const ulonglong2*)(xc + (size_t)e1 * 16);
#pragma unroll
        for (int p = 0; p < 4; p++) {
            ulonglong2 a = c0[p]; in[0][2 * p] = a.x; in[0][2 * p + 1] = a.y;
            ulonglong2 b = c1[p]; in[1][2 * p] = b.x; in[1][2 * p + 1] = b.y;
        }
    }

    // ---- h2 accumulators: 8 output-pairs per element, init with b2 ----
    u64 h2[2][8];
#pragma unroll
    for (int e = 0; e < 2; e++)
#pragma unroll
        for (int j = 0; j < 8; j++)
            h2[e][j] = sb2[j];

    // ---- Fused layers 1+2 ----
#pragma unroll 2
    for (int k = 0; k < 32; k++) {
        const ulonglong2* r1 = (const ulonglong2*)&sW1[k][0];
        ulonglong2 w01 = r1[0];
        ulonglong2 w23 = r1[1];
        ulonglong2 w45 = r1[2];
        ulonglong2 w67 = r1[3];
        float wq, b1k;
        unpack2(sWqb[k], wq, b1k);

        u64 a2[2];
#pragma unroll
        for (int e = 0; e < 2; e++) {
            u64 acc = mul2(in[e][0], w01.x);
            acc = fma2(in[e][1], w01.y, acc);
            acc = fma2(in[e][2], w23.x, acc);
            acc = fma2(in[e][3], w23.y, acc);
            acc = fma2(in[e][4], w45.x, acc);
            acc = fma2(in[e][5], w45.y, acc);
            acc = fma2(in[e][6], w67.x, acc);
            acc = fma2(in[e][7], w67.y, acc);
            float lo, hi;
            unpack2(acc, lo, hi);                 // free: register pair
            float s = fmaf(q[e], wq, b1k) + lo + hi;
            s = fmaxf(s, 0.0f);
            a2[e] = pack2(s, s);
        }

        const ulonglong2* r2 = (const ulonglong2*)&sW2[k * 8];
        ulonglong2 v01 = r2[0];
        ulonglong2 v23 = r2[1];
        ulonglong2 v45 = r2[2];
        ulonglong2 v67 = r2[3];
#pragma unroll
        for (int e = 0; e < 2; e++) {
            h2[e][0] = fma2(a2[e], v01.x, h2[e][0]);
            h2[e][1] = fma2(a2[e], v01.y, h2[e][1]);
            h2[e][2] = fma2(a2[e], v23.x, h2[e][2]);
            h2[e][3] = fma2(a2[e], v23.y, h2[e][3]);
            h2[e][4] = fma2(a2[e], v45.x, h2[e][4]);
            h2[e][5] = fma2(a2[e], v45.y, h2[e][5]);
            h2[e][6] = fma2(a2[e], v67.x, h2[e][6]);
            h2[e][7] = fma2(a2[e], v67.y, h2[e][7]);
        }
    }

    // ---- Layer 3: relu(h2) . W3 + b3, pairwise then hsum ----
    float bb = __ldg(b3);
    float o[2];
#pragma unroll
    for (int e = 0; e < 2; e++) {
        u64 acc = mul2(relu2(h2[e][0]), sW3[0]);
#pragma unroll
        for (int j = 1; j < 8; j++)
            acc = fma2(relu2(h2[e][j]), sW3[j], acc);
        float lo, hi;
        unpack2(acc, lo, hi);
        o[e] = bb + lo + hi;
    }

    out[e0] = o[0];
    out[e1] = o[1];
}

extern "C" void kernel_launch(void* const* d_in, const int* in_sizes, int n_in,
                              void* d_out, int out_size)
{
    const float* xq = (const float*)d_in[0];
    const float* xc = (const float*)d_in[1];
    const float* qp = (const float*)d_in[2];
    const float* W1 = (const float*)d_in[3];
    const float* b1 = (const float*)d_in[4];
    const float* W2 = (const float*)d_in[5];
    const float* b2 = (const float*)d_in[6];
    const float* W3 = (const float*)d_in[7];
    const float* b3 = (const float*)d_in[8];
    float* out = (float*)d_out;

    hybridq_kernel<<<NTHREADS / BLOCK, BLOCK>>>(xq, xc, qp, W1, b1, W2, b2, W3, b3, out);
}